// round 11
// baseline (speedup 1.0000x reference)
#include <cuda_runtime.h>
#include <float.h>

// Chamfer distance, B=4, N=M=4096, D=3 — symmetric, register-resident mins.
// Tile: 128 recon (rows) x 128 gt (cols) per CTA. Thread (lane,warp):
//   lane sg -> 4 src points (2 packed src-pairs), warp dg -> 32 dst points.
// Each pair distance computed ONCE: d = (np + w) + qx*x + qy*y + qz*z
// (q = -2p; packed over the 2 srcs of a pair; dst duplicated {v|v} in smem,
// warp-broadcast LDS). Row mins rm[4] and col mins cm[32] live in REGISTERS
// (j-loop fully unrolled) -> no smem traffic in the mainloop.
// Epilogue: smem combine (rows across 4 warps; cols across 32 lanes with
// rotated conflict-free reads), then atomicMax on monotone key
// 0x7F7FFFFF - bits(dist>=0); zero-initialized identity -> no init kernel.
// Last CTA decodes, sums fixed-order, resets slots. Fully deterministic.

#define BATCH 4
#define NPTS  4096
#define TPB   128
#define TILE  128                        // src tile == dst tile
#define NCHUNK (NPTS / TILE)             // 32
#define DST_PER_WARP 32
#define NSLOTS (2 * BATCH * NPTS)        // 32768 (recon then gt)
#define NCTAS (NCHUNK * NCHUNK * BATCH)  // 4096

__device__ unsigned int g_maxkey[NSLOTS];    // 0 == key(FLT_MAX): identity
__device__ unsigned int g_count = 0;

typedef unsigned long long u64;

__device__ __forceinline__ u64 pk(float a, float b) {
    u64 r;
    asm("mov.b64 %0, {%1, %2};" : "=l"(r) : "f"(a), "f"(b));
    return r;
}
__device__ __forceinline__ void upk(u64 v, float& lo, float& hi) {
    asm("mov.b64 {%0, %1}, %2;" : "=f"(lo), "=f"(hi) : "l"(v));
}
__device__ __forceinline__ u64 fma2(u64 a, u64 b, u64 c) {
    u64 d;
    asm("fma.rn.f32x2 %0, %1, %2, %3;" : "=l"(d) : "l"(a), "l"(b), "l"(c));
    return d;
}
__device__ __forceinline__ u64 add2(u64 a, u64 b) {
    u64 d;
    asm("add.rn.f32x2 %0, %1, %2;" : "=l"(d) : "l"(a), "l"(b));
    return d;
}
__device__ __forceinline__ unsigned int dist_key(float m) {
    return 0x7F7FFFFFu - __float_as_uint(fmaxf(m, 0.0f));
}

__global__ void __launch_bounds__(TPB) chamfer_sym_kernel(
    const float* __restrict__ recon,
    const float* __restrict__ gt,
    float* __restrict__ out)
{
    __shared__ ulonglong2 sXY[TILE];           // {x|x, y|y} per dst point (2KB)
    __shared__ ulonglong2 sZW[TILE];           // {z|z, w|w} per dst point (2KB)
    __shared__ float s_col[4][DST_PER_WARP][32];  // [dg][j][lane] (16KB)
    __shared__ float s_row[4][TILE];           // [dg][src]      (2KB)

    const int chunk = blockIdx.x;   // recon chunk (0..31)
    const int split = blockIdx.y;   // gt chunk    (0..31)
    const int b     = blockIdx.z;   // batch
    const int tid   = threadIdx.x;
    const int lane  = tid & 31;
    const int dg    = tid >> 5;

    // --- dst tile: one point per thread, duplicated packing ---
    {
        const float* gp = gt + ((size_t)b * NPTS + (size_t)split * TILE + tid) * 3;
        float x = gp[0], y = gp[1], z = gp[2];
        float w = fmaf(x, x, fmaf(y, y, z * z));
        sXY[tid] = make_ulonglong2(pk(x, x), pk(y, y));
        sZW[tid] = make_ulonglong2(pk(z, z), pk(w, w));
    }

    // --- src: 4 consecutive points per lane (2 packed pairs) ---
    u64 qx0, qy0, qz0, np0, qx1, qy1, qz1, np1;
    {
        const float* rp = recon + ((size_t)b * NPTS + (size_t)chunk * TILE + lane * 4) * 3;
        const float4* rv = (const float4*)rp;
        float4 f0 = rv[0];   // x0 y0 z0 x1
        float4 f1 = rv[1];   // y1 z1 x2 y2
        float4 f2 = rv[2];   // z2 x3 y3 z3
        float na = fmaf(f0.x, f0.x, fmaf(f0.y, f0.y, f0.z * f0.z));
        float nb = fmaf(f0.w, f0.w, fmaf(f1.x, f1.x, f1.y * f1.y));
        float nc = fmaf(f1.z, f1.z, fmaf(f1.w, f1.w, f2.x * f2.x));
        float nd = fmaf(f2.y, f2.y, fmaf(f2.z, f2.z, f2.w * f2.w));
        qx0 = pk(-2.0f * f0.x, -2.0f * f0.w);
        qy0 = pk(-2.0f * f0.y, -2.0f * f1.x);
        qz0 = pk(-2.0f * f0.z, -2.0f * f1.y);
        np0 = pk(na, nb);
        qx1 = pk(-2.0f * f1.z, -2.0f * f2.y);
        qy1 = pk(-2.0f * f1.w, -2.0f * f2.z);
        qz1 = pk(-2.0f * f2.x, -2.0f * f2.w);
        np1 = pk(nc, nd);
    }

    float rm0 = FLT_MAX, rm1 = FLT_MAX, rm2 = FLT_MAX, rm3 = FLT_MAX;
    float cm[DST_PER_WARP];
    #pragma unroll
    for (int j = 0; j < DST_PER_WARP; ++j) cm[j] = FLT_MAX;

    __syncthreads();

    // --- mainloop: fully unrolled, register-only mins, broadcast LDS ---
    #pragma unroll
    for (int j = 0; j < DST_PER_WARP; ++j) {
        ulonglong2 XY = sXY[dg * DST_PER_WARP + j];
        ulonglong2 ZW = sZW[dg * DST_PER_WARP + j];

        u64 d0 = fma2(qx0, XY.x, fma2(qy0, XY.y, fma2(qz0, ZW.x, add2(np0, ZW.y))));
        u64 d1 = fma2(qx1, XY.x, fma2(qy1, XY.y, fma2(qz1, ZW.x, add2(np1, ZW.y))));

        float l0, h0, l1, h1;
        upk(d0, l0, h0);
        upk(d1, l1, h1);
        rm0 = fminf(rm0, l0);
        rm1 = fminf(rm1, h0);
        rm2 = fminf(rm2, l1);
        rm3 = fminf(rm3, h1);
        cm[j] = fminf(cm[j], fminf(fminf(l0, h0), fminf(l1, h1)));
    }

    // --- epilogue: stage partial mins to smem ---
    s_row[dg][lane * 4 + 0] = rm0;
    s_row[dg][lane * 4 + 1] = rm1;
    s_row[dg][lane * 4 + 2] = rm2;
    s_row[dg][lane * 4 + 3] = rm3;
    #pragma unroll
    for (int j = 0; j < DST_PER_WARP; ++j)
        s_col[dg][j][lane] = cm[j];
    __syncthreads();

    // Row combine: thread t owns src t (min over 4 warps), -> recon slot.
    {
        float v = s_row[0][tid];
        v = fminf(v, s_row[1][tid]);
        v = fminf(v, s_row[2][tid]);
        v = fminf(v, s_row[3][tid]);
        atomicMax(&g_maxkey[b * NPTS + chunk * TILE + tid], dist_key(v));
    }
    // Col combine: thread t owns dst t (min over 32 lanes, rotated reads).
    {
        const int dgo = tid >> 5;
        const int jo  = tid & 31;
        float v = FLT_MAX;
        #pragma unroll 8
        for (int l = 0; l < 32; ++l)
            v = fminf(v, s_col[dgo][jo][(l + jo) & 31]);
        atomicMax(&g_maxkey[BATCH * NPTS + b * NPTS + split * TILE + tid],
                  dist_key(v));
    }

    // --- elect last CTA to finalize ---
    __shared__ unsigned int s_last;
    __threadfence();
    __syncthreads();
    if (tid == 0) {
        unsigned int old = atomicAdd(&g_count, 1u);
        s_last = (old == NCTAS - 1) ? 1u : 0u;
    }
    __syncthreads();

    if (s_last) {
        __threadfence();   // all atomics visible
        float acc = 0.0f;
        const uint4* mv = (const uint4*)g_maxkey;
        #pragma unroll 4
        for (int s = tid; s < NSLOTS / 4; s += TPB) {
            uint4 v = mv[s];
            acc += __uint_as_float(0x7F7FFFFFu - v.x)
                 + __uint_as_float(0x7F7FFFFFu - v.y)
                 + __uint_as_float(0x7F7FFFFFu - v.z)
                 + __uint_as_float(0x7F7FFFFFu - v.w);
        }
        __shared__ float sred[TPB];
        sred[tid] = acc;
        __syncthreads();

        // Reset slots to the identity (0) for the next graph replay.
        uint4* mw = (uint4*)g_maxkey;
        const uint4 z4 = make_uint4(0u, 0u, 0u, 0u);
        #pragma unroll 4
        for (int s = tid; s < NSLOTS / 4; s += TPB) mw[s] = z4;

        #pragma unroll
        for (int s = TPB / 2; s > 0; s >>= 1) {
            if (tid < s) sred[tid] += sred[tid + s];
            __syncthreads();
        }
        if (tid == 0) {
            out[0] = sred[0] / (float)NSLOTS;   // == (mean1 + mean2) / 2
            g_count = 0;                        // reset for next replay
        }
    }
}

extern "C" void kernel_launch(void* const* d_in, const int* in_sizes, int n_in,
                              void* d_out, int out_size)
{
    const float* recon = (const float*)d_in[0];
    const float* gt    = (const float*)d_in[1];
    float* out = (float*)d_out;

    dim3 grid(NCHUNK, NCHUNK, BATCH);   // 32 x 32 x 4 = 4096 CTAs
    chamfer_sym_kernel<<<grid, TPB>>>(recon, gt, out);
}

// round 12
// speedup vs baseline: 1.1455x; 1.1455x over previous
#include <cuda_runtime.h>
#include <cuda_bf16.h>
#include <float.h>

// Chamfer distance, B=4, N=M=4096, D=3 — tensor-core (warp mma.sync) version.
// One m16n8k16 bf16 MMA produces 128 FINAL squared distances:
//   A row (src p): [qhi qhi? see map] with q=-2p, np=|p|^2 split into bf16 hi/lo
//   B row (dst g): g split hi/lo, w=|g|^2 split hi/lo
//   k map  A: qhi.xyz | qlo.xyz | qhi.xyz | qlo.xyz | np_hi np_lo 1 1
//          B: ghi.xyz | ghi.xyz | glo.xyz | glo.xyz | 1 1 w_hi w_lo
//   dot = (qhi+qlo).(ghi+glo) + np + w = |p-g|^2  (exact split, fp32 accum).
// Row mins in registers (d-fragment layout known), both directions as
// role-swapped passes (blockIdx.z). Cross-CTA combine: atomicMax on monotone
// key 0x7F7FFFFF - bits(d>=0); zero-initialized identity -> no init kernel.
// Last CTA decodes/sums fixed-order, resets slots. Deterministic.

#define BATCH 4
#define NPTS  4096
#define TPB   128
#define NWARP 4
#define ROWS_PER_CTA 64
#define ROWCHUNKS (NPTS / ROWS_PER_CTA)      // 64
#define COLSPLIT 2
#define COLS_PER_CTA (NPTS / COLSPLIT)       // 2048
#define STAGE_COLS 256
#define NSTAGES (COLS_PER_CTA / STAGE_COLS)  // 8
#define TILES_PER_STAGE (STAGE_COLS / 8)     // 32
#define ROW_STRIDE 24                        // bf16 elems per smem row (48B, cf-free LDSM)
#define NSLOTS (2 * BATCH * NPTS)            // 32768
#define NCTAS (ROWCHUNKS * COLSPLIT * BATCH * 2)  // 1024

__device__ unsigned int g_maxkey[NSLOTS];    // 0 == key(FLT_MAX): identity
__device__ unsigned int g_count = 0;

__device__ __forceinline__ unsigned int dist_key(float m) {
    return 0x7F7FFFFFu - __float_as_uint(fmaxf(m, 0.0f));
}
__device__ __forceinline__ void bsplit(float v, unsigned short& hb, unsigned short& lb) {
    __nv_bfloat16 h = __float2bfloat16_rn(v);
    hb = __bfloat16_as_ushort(h);
    lb = __bfloat16_as_ushort(__float2bfloat16_rn(v - __bfloat162float(h)));
}
__device__ __forceinline__ unsigned int pk16(unsigned short lo, unsigned short hi) {
    return (unsigned int)lo | ((unsigned int)hi << 16);
}
__device__ __forceinline__ unsigned int smaddr(const void* p) {
    return (unsigned int)__cvta_generic_to_shared(p);
}

// A-row encode: [qh qh qh ql ql ql] x2, np_hi, np_lo, 1, 1
__device__ __forceinline__ void encodeA(unsigned short* row, float px, float py, float pz) {
    unsigned short qhx, qlx, qhy, qly, qhz, qlz, nh, nl;
    bsplit(-2.0f * px, qhx, qlx);
    bsplit(-2.0f * py, qhy, qly);
    bsplit(-2.0f * pz, qhz, qlz);
    bsplit(fmaf(px, px, fmaf(py, py, pz * pz)), nh, nl);
    const unsigned short one = 0x3F80;
    uint4 v0 = make_uint4(pk16(qhx, qhy), pk16(qhz, qlx), pk16(qly, qlz), pk16(qhx, qhy));
    uint4 v1 = make_uint4(pk16(qhz, qlx), pk16(qly, qlz), pk16(nh, nl), pk16(one, one));
    *(uint4*)(row)     = v0;
    *(uint4*)(row + 8) = v1;
}
// B-row encode: gh gh gh | gh gh gh? no: [gh3, gh3, gl3, gl3, 1, 1, wh, wl]
__device__ __forceinline__ void encodeB(unsigned short* row, float gx, float gy, float gz) {
    unsigned short ghx, glx, ghy, gly, ghz, glz, wh, wl;
    bsplit(gx, ghx, glx);
    bsplit(gy, ghy, gly);
    bsplit(gz, ghz, glz);
    bsplit(fmaf(gx, gx, fmaf(gy, gy, gz * gz)), wh, wl);
    const unsigned short one = 0x3F80;
    uint4 v0 = make_uint4(pk16(ghx, ghy), pk16(ghz, ghx), pk16(ghy, ghz), pk16(glx, gly));
    uint4 v1 = make_uint4(pk16(glz, glx), pk16(gly, glz), pk16(one, one), pk16(wh, wl));
    *(uint4*)(row)     = v0;
    *(uint4*)(row + 8) = v1;
}

__global__ void __launch_bounds__(TPB) chamfer_mma_kernel(
    const float* __restrict__ recon,
    const float* __restrict__ gt,
    float* __restrict__ out)
{
    __shared__ __align__(16) unsigned short sA[ROWS_PER_CTA * ROW_STRIDE];  // 3 KB
    __shared__ __align__(16) unsigned short sB[STAGE_COLS * ROW_STRIDE];    // 12 KB

    const int chunk  = blockIdx.x;          // row chunk (0..63)
    const int b      = blockIdx.y >> 1;     // batch
    const int csplit = blockIdx.y & 1;      // column half
    const int dir    = blockIdx.z;          // 0: recon rows; 1: gt rows
    const int tid    = threadIdx.x;
    const int lane   = tid & 31;
    const int wid    = tid >> 5;

    const float* src = dir ? gt : recon;    // rows (A)
    const float* dst = dir ? recon : gt;    // cols (B)

    // --- encode A (64 rows) ---
    if (tid < ROWS_PER_CTA) {
        const float* sp = src + ((size_t)b * NPTS + chunk * ROWS_PER_CTA + tid) * 3;
        encodeA(&sA[tid * ROW_STRIDE], sp[0], sp[1], sp[2]);
    }
    __syncthreads();

    // --- load A fragments once per warp (rows wid*16 .. wid*16+15) ---
    unsigned int a0, a1, a2, a3;
    {
        unsigned int aaddr = smaddr(sA)
                           + (wid * 16 + (lane & 15)) * (ROW_STRIDE * 2)
                           + ((lane >> 4) << 4);
        asm volatile("ldmatrix.sync.aligned.m8n8.x4.shared.b16 {%0,%1,%2,%3}, [%4];"
                     : "=r"(a0), "=r"(a1), "=r"(a2), "=r"(a3) : "r"(aaddr));
    }

    float rm0 = FLT_MAX, rm1 = FLT_MAX;
    const unsigned int bLaneOff = (lane & 7) * (ROW_STRIDE * 2) + ((lane & 8) ? 16 : 0);
    const float fz = 0.0f;

    for (int s = 0; s < NSTAGES; ++s) {
        __syncthreads();   // previous stage fully consumed
        // encode 256 dst cols (2 points per thread; 24B-aligned float2 loads)
        {
            const float2* gp = (const float2*)(dst
                + ((size_t)b * NPTS + csplit * COLS_PER_CTA + s * STAGE_COLS) * 3
                + 6 * tid);
            float2 f0 = gp[0];   // x0 y0
            float2 f1 = gp[1];   // z0 x1
            float2 f2 = gp[2];   // y1 z1
            encodeB(&sB[(2 * tid)     * ROW_STRIDE], f0.x, f0.y, f1.x);
            encodeB(&sB[(2 * tid + 1) * ROW_STRIDE], f1.y, f2.x, f2.y);
        }
        __syncthreads();

        unsigned int baddr = smaddr(sB) + bLaneOff;
        #pragma unroll 8
        for (int t = 0; t < TILES_PER_STAGE; ++t) {
            unsigned int b0, b1;
            asm volatile("ldmatrix.sync.aligned.m8n8.x2.shared.b16 {%0,%1}, [%2];"
                         : "=r"(b0), "=r"(b1) : "r"(baddr));
            baddr += 8 * (ROW_STRIDE * 2);

            float d0, d1, d2, d3;
            asm volatile(
                "mma.sync.aligned.m16n8k16.row.col.f32.bf16.bf16.f32 "
                "{%0,%1,%2,%3}, {%4,%5,%6,%7}, {%8,%9}, {%10,%11,%12,%13};"
                : "=f"(d0), "=f"(d1), "=f"(d2), "=f"(d3)
                : "r"(a0), "r"(a1), "r"(a2), "r"(a3), "r"(b0), "r"(b1),
                  "f"(fz), "f"(fz), "f"(fz), "f"(fz));

            rm0 = fminf(rm0, fminf(d0, d1));   // row = group
            rm1 = fminf(rm1, fminf(d2, d3));   // row = group + 8
        }
    }

    // --- row-min combine across the 4 lanes sharing a row (cols) ---
    rm0 = fminf(rm0, __shfl_xor_sync(0xffffffffu, rm0, 1));
    rm0 = fminf(rm0, __shfl_xor_sync(0xffffffffu, rm0, 2));
    rm1 = fminf(rm1, __shfl_xor_sync(0xffffffffu, rm1, 1));
    rm1 = fminf(rm1, __shfl_xor_sync(0xffffffffu, rm1, 2));
    if ((lane & 3) == 0) {
        const int row   = chunk * ROWS_PER_CTA + wid * 16 + (lane >> 2);
        const int sbase = dir * BATCH * NPTS + b * NPTS;
        atomicMax(&g_maxkey[sbase + row],     dist_key(rm0));
        atomicMax(&g_maxkey[sbase + row + 8], dist_key(rm1));
    }

    // --- elect last CTA to finalize ---
    __shared__ unsigned int s_last;
    __threadfence();
    __syncthreads();
    if (tid == 0) {
        unsigned int old = atomicAdd(&g_count, 1u);
        s_last = (old == NCTAS - 1) ? 1u : 0u;
    }
    __syncthreads();

    if (s_last) {
        __threadfence();   // all atomics visible
        float acc = 0.0f;
        const uint4* mv = (const uint4*)g_maxkey;
        #pragma unroll 4
        for (int s = tid; s < NSLOTS / 4; s += TPB) {
            uint4 v = mv[s];
            acc += __uint_as_float(0x7F7FFFFFu - v.x)
                 + __uint_as_float(0x7F7FFFFFu - v.y)
                 + __uint_as_float(0x7F7FFFFFu - v.z)
                 + __uint_as_float(0x7F7FFFFFu - v.w);
        }
        __shared__ float sred[TPB];
        sred[tid] = acc;
        __syncthreads();

        // Reset slots to identity for the next graph replay.
        uint4* mw = (uint4*)g_maxkey;
        const uint4 z4 = make_uint4(0u, 0u, 0u, 0u);
        #pragma unroll 4
        for (int s = tid; s < NSLOTS / 4; s += TPB) mw[s] = z4;

        #pragma unroll
        for (int s = TPB / 2; s > 0; s >>= 1) {
            if (tid < s) sred[tid] += sred[tid + s];
            __syncthreads();
        }
        if (tid == 0) {
            out[0] = sred[0] / (float)NSLOTS;   // == (mean1 + mean2) / 2
            g_count = 0;                        // reset for next replay
        }
    }
}

extern "C" void kernel_launch(void* const* d_in, const int* in_sizes, int n_in,
                              void* d_out, int out_size)
{
    const float* recon = (const float*)d_in[0];
    const float* gt    = (const float*)d_in[1];
    float* out = (float*)d_out;

    dim3 grid(ROWCHUNKS, COLSPLIT * BATCH, 2);   // 64 x 8 x 2 = 1024 CTAs
    chamfer_mma_kernel<<<grid, TPB>>>(recon, gt, out);
}

// round 13
// speedup vs baseline: 1.2391x; 1.0817x over previous
#include <cuda_runtime.h>
#include <cuda_bf16.h>
#include <float.h>

// Chamfer distance, B=4, N=M=4096, D=3 — tensor-core mma.sync, v2.
// One m16n8k16 bf16 MMA yields 128 FINAL squared distances via exact 2-term
// bf16 split (k map:  A: qhi.xyz qlo.xyz qhi.xyz qlo.xyz np_hi np_lo 1 1
//                     B: ghi.xyz ghi.xyz glo.xyz glo.xyz 1 1 w_hi w_lo
//  dot = (qhi+qlo).(ghi+glo) + np + w = |p-g|^2, fp32 accum).
// v2: 32 rows/warp (2 A frags), n=16 B frags (ldmatrix.x4 -> 2 MMAs),
// so 1 LDSM feeds 4 HMMAs; COLSPLIT=4 + double-buffered B stages (1 sync
// per stage, encode overlapped with MMA). Row mins in regs; both directions
// as role-swapped passes (blockIdx.z). Cross-CTA combine: atomicMax on
// monotone key 0x7F7FFFFF - bits(d>=0) (zero-init identity, no init kernel);
// last CTA decodes/sums fixed-order, resets slots. Deterministic.

#define BATCH 4
#define NPTS  4096
#define TPB   128
#define ROWS_PER_CTA 128                     // 32 rows per warp
#define ROWCHUNKS (NPTS / ROWS_PER_CTA)      // 32
#define COLSPLIT 4
#define COLS_PER_CTA (NPTS / COLSPLIT)       // 1024
#define STAGE_COLS 256
#define NSTAGES (COLS_PER_CTA / STAGE_COLS)  // 4
#define UNITS_PER_STAGE (STAGE_COLS / 16)    // 16 (n=16 per ldmatrix.x4)
#define ROW_STRIDE 24                        // bf16 elems per smem row (48B)
#define NSLOTS (2 * BATCH * NPTS)            // 32768
#define NCTAS (ROWCHUNKS * COLSPLIT * BATCH * 2)  // 1024

__device__ unsigned int g_maxkey[NSLOTS];    // 0 == key(FLT_MAX): identity
__device__ unsigned int g_count = 0;

__device__ __forceinline__ unsigned int dist_key(float m) {
    return 0x7F7FFFFFu - __float_as_uint(fmaxf(m, 0.0f));
}
__device__ __forceinline__ void bsplit(float v, unsigned short& hb, unsigned short& lb) {
    __nv_bfloat16 h = __float2bfloat16_rn(v);
    hb = __bfloat16_as_ushort(h);
    lb = __bfloat16_as_ushort(__float2bfloat16_rn(v - __bfloat162float(h)));
}
__device__ __forceinline__ unsigned int pk16(unsigned short lo, unsigned short hi) {
    return (unsigned int)lo | ((unsigned int)hi << 16);
}
__device__ __forceinline__ unsigned int smaddr(const void* p) {
    return (unsigned int)__cvta_generic_to_shared(p);
}

__device__ __forceinline__ void encodeA(unsigned short* row, float px, float py, float pz) {
    unsigned short qhx, qlx, qhy, qly, qhz, qlz, nh, nl;
    bsplit(-2.0f * px, qhx, qlx);
    bsplit(-2.0f * py, qhy, qly);
    bsplit(-2.0f * pz, qhz, qlz);
    bsplit(fmaf(px, px, fmaf(py, py, pz * pz)), nh, nl);
    const unsigned short one = 0x3F80;
    *(uint4*)(row)     = make_uint4(pk16(qhx, qhy), pk16(qhz, qlx), pk16(qly, qlz), pk16(qhx, qhy));
    *(uint4*)(row + 8) = make_uint4(pk16(qhz, qlx), pk16(qly, qlz), pk16(nh, nl), pk16(one, one));
}
__device__ __forceinline__ void encodeB(unsigned short* row, float gx, float gy, float gz) {
    unsigned short ghx, glx, ghy, gly, ghz, glz, wh, wl;
    bsplit(gx, ghx, glx);
    bsplit(gy, ghy, gly);
    bsplit(gz, ghz, glz);
    bsplit(fmaf(gx, gx, fmaf(gy, gy, gz * gz)), wh, wl);
    const unsigned short one = 0x3F80;
    *(uint4*)(row)     = make_uint4(pk16(ghx, ghy), pk16(ghz, ghx), pk16(ghy, ghz), pk16(glx, gly));
    *(uint4*)(row + 8) = make_uint4(pk16(glz, glx), pk16(gly, glz), pk16(one, one), pk16(wh, wl));
}

__global__ void __launch_bounds__(TPB) chamfer_mma_kernel(
    const float* __restrict__ recon,
    const float* __restrict__ gt,
    float* __restrict__ out)
{
    __shared__ __align__(16) unsigned short sA[ROWS_PER_CTA * ROW_STRIDE];      // 6 KB
    __shared__ __align__(16) unsigned short sB[2][STAGE_COLS * ROW_STRIDE];     // 24 KB

    const int chunk  = blockIdx.x;          // row chunk (0..31)
    const int b      = blockIdx.y >> 2;     // batch
    const int csplit = blockIdx.y & 3;      // column quarter
    const int dir    = blockIdx.z;          // 0: recon rows; 1: gt rows
    const int tid    = threadIdx.x;
    const int lane   = tid & 31;
    const int wid    = tid >> 5;

    const float* src = dir ? gt : recon;    // rows (A)
    const float* dst = dir ? recon : gt;    // cols (B)
    const size_t colbase = (size_t)b * NPTS + csplit * COLS_PER_CTA;

    // --- encode A (128 rows, 1/thread) ---
    {
        const float* sp = src + ((size_t)b * NPTS + chunk * ROWS_PER_CTA + tid) * 3;
        encodeA(&sA[tid * ROW_STRIDE], sp[0], sp[1], sp[2]);
    }
    // --- encode B stage 0 into buffer 0 (2 cols/thread) ---
    {
        const float2* gp = (const float2*)(dst + colbase * 3 + 6 * tid);
        float2 f0 = gp[0], f1 = gp[1], f2 = gp[2];
        encodeB(&sB[0][(2 * tid)     * ROW_STRIDE], f0.x, f0.y, f1.x);
        encodeB(&sB[0][(2 * tid + 1) * ROW_STRIDE], f1.y, f2.x, f2.y);
    }
    __syncthreads();

    // --- load 2 A fragments per warp (rows wid*32 .. wid*32+31) ---
    unsigned int a0[4], a1[4];
    {
        unsigned int base = smaddr(sA) + ((lane & 15) * ROW_STRIDE * 2) + ((lane >> 4) << 4);
        unsigned int ad0 = base + (wid * 32) * (ROW_STRIDE * 2);
        unsigned int ad1 = base + (wid * 32 + 16) * (ROW_STRIDE * 2);
        asm volatile("ldmatrix.sync.aligned.m8n8.x4.shared.b16 {%0,%1,%2,%3}, [%4];"
                     : "=r"(a0[0]), "=r"(a0[1]), "=r"(a0[2]), "=r"(a0[3]) : "r"(ad0));
        asm volatile("ldmatrix.sync.aligned.m8n8.x4.shared.b16 {%0,%1,%2,%3}, [%4];"
                     : "=r"(a1[0]), "=r"(a1[1]), "=r"(a1[2]), "=r"(a1[3]) : "r"(ad1));
    }

    float rm0 = FLT_MAX, rm1 = FLT_MAX, rm2 = FLT_MAX, rm3 = FLT_MAX;
    // B ldmatrix.x4 lane pattern: cols (lane&7) + ((lane&16)?8:0), k-half by lane&8.
    const unsigned int bLaneOff = ((lane & 7) + ((lane >> 4) << 3)) * (ROW_STRIDE * 2)
                                + ((lane & 8) ? 16 : 0);
    const float fz = 0.0f;

#define DO_MMA(AF, BB0, BB1, RA, RB)                                            \
    {                                                                           \
        float d0, d1, d2, d3;                                                   \
        asm volatile(                                                           \
            "mma.sync.aligned.m16n8k16.row.col.f32.bf16.bf16.f32 "              \
            "{%0,%1,%2,%3}, {%4,%5,%6,%7}, {%8,%9}, {%10,%11,%12,%13};"         \
            : "=f"(d0), "=f"(d1), "=f"(d2), "=f"(d3)                            \
            : "r"(AF[0]), "r"(AF[1]), "r"(AF[2]), "r"(AF[3]),                   \
              "r"(BB0), "r"(BB1), "f"(fz), "f"(fz), "f"(fz), "f"(fz));          \
        RA = fminf(RA, fminf(d0, d1));                                          \
        RB = fminf(RB, fminf(d2, d3));                                          \
    }

    for (int s = 0; s < NSTAGES; ++s) {
        // Encode next stage into the idle buffer (overlaps with MMA below).
        if (s + 1 < NSTAGES) {
            const float2* gp = (const float2*)(dst
                + (colbase + (size_t)(s + 1) * STAGE_COLS) * 3 + 6 * tid);
            float2 f0 = gp[0], f1 = gp[1], f2 = gp[2];
            unsigned short* buf = sB[(s + 1) & 1];
            encodeB(&buf[(2 * tid)     * ROW_STRIDE], f0.x, f0.y, f1.x);
            encodeB(&buf[(2 * tid + 1) * ROW_STRIDE], f1.y, f2.x, f2.y);
        }

        unsigned int baddr = smaddr(sB[s & 1]) + bLaneOff;
        #pragma unroll
        for (int t = 0; t < UNITS_PER_STAGE; ++t) {
            unsigned int b0, b1, b2, b3;
            asm volatile("ldmatrix.sync.aligned.m8n8.x4.shared.b16 {%0,%1,%2,%3}, [%4];"
                         : "=r"(b0), "=r"(b1), "=r"(b2), "=r"(b3) : "r"(baddr));
            baddr += 16 * (ROW_STRIDE * 2);

            DO_MMA(a0, b0, b1, rm0, rm1);   // rows wid*32+0..15, cols t*16+0..7
            DO_MMA(a0, b2, b3, rm0, rm1);   // cols t*16+8..15
            DO_MMA(a1, b0, b1, rm2, rm3);   // rows wid*32+16..31
            DO_MMA(a1, b2, b3, rm2, rm3);
        }
        __syncthreads();   // stage consumed + next stage encoded
    }
#undef DO_MMA

    // --- row-min combine across the 4 lanes sharing a row ---
    rm0 = fminf(rm0, __shfl_xor_sync(0xffffffffu, rm0, 1));
    rm0 = fminf(rm0, __shfl_xor_sync(0xffffffffu, rm0, 2));
    rm1 = fminf(rm1, __shfl_xor_sync(0xffffffffu, rm1, 1));
    rm1 = fminf(rm1, __shfl_xor_sync(0xffffffffu, rm1, 2));
    rm2 = fminf(rm2, __shfl_xor_sync(0xffffffffu, rm2, 1));
    rm2 = fminf(rm2, __shfl_xor_sync(0xffffffffu, rm2, 2));
    rm3 = fminf(rm3, __shfl_xor_sync(0xffffffffu, rm3, 1));
    rm3 = fminf(rm3, __shfl_xor_sync(0xffffffffu, rm3, 2));
    if ((lane & 3) == 0) {
        const int row   = chunk * ROWS_PER_CTA + wid * 32 + (lane >> 2);
        const int sbase = dir * BATCH * NPTS + b * NPTS;
        atomicMax(&g_maxkey[sbase + row],      dist_key(rm0));
        atomicMax(&g_maxkey[sbase + row + 8],  dist_key(rm1));
        atomicMax(&g_maxkey[sbase + row + 16], dist_key(rm2));
        atomicMax(&g_maxkey[sbase + row + 24], dist_key(rm3));
    }

    // --- elect last CTA to finalize ---
    __shared__ unsigned int s_last;
    __threadfence();
    __syncthreads();
    if (tid == 0) {
        unsigned int old = atomicAdd(&g_count, 1u);
        s_last = (old == NCTAS - 1) ? 1u : 0u;
    }
    __syncthreads();

    if (s_last) {
        __threadfence();   // all atomics visible
        float acc = 0.0f;
        const uint4* mv = (const uint4*)g_maxkey;
        #pragma unroll 4
        for (int s = tid; s < NSLOTS / 4; s += TPB) {
            uint4 v = mv[s];
            acc += __uint_as_float(0x7F7FFFFFu - v.x)
                 + __uint_as_float(0x7F7FFFFFu - v.y)
                 + __uint_as_float(0x7F7FFFFFu - v.z)
                 + __uint_as_float(0x7F7FFFFFu - v.w);
        }
        __shared__ float sred[TPB];
        sred[tid] = acc;
        __syncthreads();

        // Reset slots to identity for the next graph replay.
        uint4* mw = (uint4*)g_maxkey;
        const uint4 z4 = make_uint4(0u, 0u, 0u, 0u);
        #pragma unroll 4
        for (int s = tid; s < NSLOTS / 4; s += TPB) mw[s] = z4;

        #pragma unroll
        for (int s = TPB / 2; s > 0; s >>= 1) {
            if (tid < s) sred[tid] += sred[tid + s];
            __syncthreads();
        }
        if (tid == 0) {
            out[0] = sred[0] / (float)NSLOTS;   // == (mean1 + mean2) / 2
            g_count = 0;                        // reset for next replay
        }
    }
}

extern "C" void kernel_launch(void* const* d_in, const int* in_sizes, int n_in,
                              void* d_out, int out_size)
{
    const float* recon = (const float*)d_in[0];
    const float* gt    = (const float*)d_in[1];
    float* out = (float*)d_out;

    dim3 grid(ROWCHUNKS, COLSPLIT * BATCH, 2);   // 32 x 16 x 2 = 1024 CTAs
    chamfer_mma_kernel<<<grid, TPB>>>(recon, gt, out);
}